// round 3
// baseline (speedup 1.0000x reference)
#include <cuda_runtime.h>
#include <cstdint>

#define SEQ   4096
#define BATCH 64
#define DIM   96
#define HID   128
#define NROWS (SEQ*BATCH)

using u64 = unsigned long long;

// ---------------- scratch ----------------------------------------------------
__device__ float g_zq [(size_t)SEQ*1024*64];  // [t][n][b], n = cell*512+gate*128+unit (reused by both layers)
__device__ float g_ys0[(size_t)NROWS*256];    // [t][b][2H]
__device__ float g_ys1[(size_t)NROWS*256];
__device__ float g_h  [2][2][2][HID*BATCH];   // [layer][cell][parity][unit*64+b]
__device__ int   g_flag[2][2][32];            // [layer][cell][p] monotonic epochs

// ---------------- helpers ----------------------------------------------------
__device__ __forceinline__ float sigm(float x)   { return 1.f/(1.f+__expf(-x)); }
__device__ __forceinline__ float tanh_s(float x) { float e=__expf(2.f*x); return 1.f-2.f/(e+1.f); }
__device__ __forceinline__ void ffma2(u64 &d, u64 a, u64 b) {
    asm volatile("fma.rn.f32x2 %0, %1, %2, %0;" : "+l"(d) : "l"(a), "l"(b));
}
__device__ __forceinline__ void lds2(u64 &a, u64 &b, uint32_t addr) {
    asm volatile("ld.shared.v2.u64 {%0,%1}, [%2];" : "=l"(a), "=l"(b) : "r"(addr));
}
__device__ __forceinline__ void unpk(float &lo, float &hi, u64 v) {
    asm volatile("mov.b64 {%0,%1}, %2;" : "=f"(lo), "=f"(hi) : "l"(v));
}
__device__ __forceinline__ int ldacq(const int* p) {
    int v; asm volatile("ld.acquire.gpu.global.s32 %0, [%1];" : "=r"(v) : "l"(p) : "memory"); return v;
}

__global__ void init_kernel() {
    int tid = blockIdx.x*blockDim.x + threadIdx.x, n = gridDim.x*blockDim.x;
    for (int i = tid; i < 2*2*32; i += n) ((int*)g_flag)[i] = 0;
    for (int i = tid; i < 2*2*2*HID*BATCH; i += n) ((float*)g_h)[i] = 0.f;
}

// ---------------- GEMM: zq[t][n][b] = bias[n] + sum_k A[t*64+b][k]*W[n][k] ----
// Block: 2 timesteps (128 rows) x 128 n. 256 thr; ty=n-octet, tx=b-quad (x2 t).
template<int K, int LAYER>
__global__ void __launch_bounds__(256) gemm_kernel(
    const float* __restrict__ Aext,
    const float* __restrict__ Wf, const float* __restrict__ Wb,
    const float* __restrict__ bf, const float* __restrict__ bb)
{
    __shared__ float  As[16][132];   // [k][m]  m = 2t x 64b
    __shared__ float2 Bs[16][132];   // [k][n]  duplicated pairs

    const float* A = (LAYER == 0) ? Aext : (const float*)g_ys0;
    const int t0  = blockIdx.y * 2;
    const int n0  = blockIdx.x * 128;
    const int tid = threadIdx.x;
    const int ty  = tid >> 4;        // 8 n each
    const int tx  = tid & 15;        // b quads: tx*4 (t0) and 64+tx*4 (t1)

    const float* W    = (n0 < 512) ? (Wf + (size_t)n0*K) : (Wb + (size_t)(n0-512)*K);
    const float* bias = (n0 < 512) ? (bf + n0) : (bb + (n0-512));

    u64 acc[8][4];
#pragma unroll
    for (int i = 0; i < 8; i++) { acc[i][0]=acc[i][1]=acc[i][2]=acc[i][3]=0ull; }

    uint32_t as_s = (uint32_t)__cvta_generic_to_shared(&As[0][0]);
    uint32_t bs_s = (uint32_t)__cvta_generic_to_shared(&Bs[0][0]);

    for (int k0 = 0; k0 < K; k0 += 16) {
#pragma unroll
        for (int it = 0; it < 2; it++) {
            int q = tid + it*256;                      // A: 512 float4
            int r = q >> 2, kq = q & 3;
            float4 a = *(const float4*)(A + (size_t)(t0*64 + r)*K + k0 + kq*4);
            As[kq*4+0][r]=a.x; As[kq*4+1][r]=a.y; As[kq*4+2][r]=a.z; As[kq*4+3][r]=a.w;
        }
#pragma unroll
        for (int it = 0; it < 2; it++) {
            int q = tid + it*256;                      // B: 512 float4
            int nn = q & 127, kq = q >> 7;
            float4 w = *(const float4*)(W + (size_t)nn*K + k0 + kq*4);
            Bs[kq*4+0][nn]=make_float2(w.x,w.x); Bs[kq*4+1][nn]=make_float2(w.y,w.y);
            Bs[kq*4+2][nn]=make_float2(w.z,w.z); Bs[kq*4+3][nn]=make_float2(w.w,w.w);
        }
        __syncthreads();
#pragma unroll
        for (int kk = 0; kk < 16; kk++) {
            u64 a00,a01,a10,a11;
            lds2(a00,a01, as_s + (kk*132 + tx*4)*4);
            lds2(a10,a11, as_s + (kk*132 + 64 + tx*4)*4);
#pragma unroll
            for (int j = 0; j < 4; j++) {
                u64 w0,w1;
                lds2(w0,w1, bs_s + (kk*132 + ty*8 + 2*j)*8);
                ffma2(acc[2*j  ][0],a00,w0); ffma2(acc[2*j  ][1],a01,w0);
                ffma2(acc[2*j  ][2],a10,w0); ffma2(acc[2*j  ][3],a11,w0);
                ffma2(acc[2*j+1][0],a00,w1); ffma2(acc[2*j+1][1],a01,w1);
                ffma2(acc[2*j+1][2],a10,w1); ffma2(acc[2*j+1][3],a11,w1);
            }
        }
        __syncthreads();
    }
#pragma unroll
    for (int i = 0; i < 8; i++) {
        int nl = ty*8 + i;
        float bv = __ldg(bias + nl);
        float4 o0, o1;
        unpk(o0.x,o0.y,acc[i][0]); unpk(o0.z,o0.w,acc[i][1]);
        unpk(o1.x,o1.y,acc[i][2]); unpk(o1.z,o1.w,acc[i][3]);
        o0.x+=bv; o0.y+=bv; o0.z+=bv; o0.w+=bv;
        o1.x+=bv; o1.y+=bv; o1.z+=bv; o1.w+=bv;
        *(float4*)(g_zq + ((size_t)t0*1024 + n0 + nl)*64 + tx*4)     = o0;
        *(float4*)(g_zq + ((size_t)(t0+1)*1024 + n0 + nl)*64 + tx*4) = o1;
    }
}

// ---------------- recurrence -------------------------------------------------
// 64 CTAs: cell = bx>>5, p = bx&31 (units p*4..p*4+3), 256 threads, dyn smem.
// k-loop lane map: r(row=gate*4+u) = b7b4b3b2, q(batch-pair-pair) = b6b5b1b0.
// Epilogue: thread (u=tid&3, b=tid>>2) holds c for one batch across all t.
#define REC_SMEM ((8192 + 4160 + 1056) * 4)

template<int LAYER>
__global__ void __launch_bounds__(256) recur_kernel(
    const float* __restrict__ whhf, const float* __restrict__ whhb)
{
    extern __shared__ float sm[];
    float*  hs   = sm;               // [128 k][64 b] floats (=[k][32] f32x2)
    float2* ws2  = (float2*)(sm + 8192);  // [16 r][130] dup pairs
    float*  zsm  = sm + 8192 + 4160;      // [16 r][66]

    const int tid  = threadIdx.x;
    const int cell = blockIdx.x >> 5;
    const int p    = blockIdx.x & 31;
    const float* whh = cell ? whhb : whhf;
    float* ys = LAYER ? g_ys1 : g_ys0;

    for (int idx = tid; idx < 2048; idx += 256) {
        int r = idx >> 7, k = idx & 127;
        float w = whh[(size_t)((r>>2)*128 + p*4 + (r&3))*128 + k];
        ws2[r*130 + k] = make_float2(w, w);
    }

    const int lr = ((tid>>7)<<3) | ((tid>>2)&7);   // 0..15
    const int lq = ((tid>>5)&3)*4 + (tid&3);       // 0..15
    const int u  = tid & 3;
    const int b  = tid >> 2;

    uint32_t hs_s = (uint32_t)__cvta_generic_to_shared(hs);
    const uint32_t ha = hs_s + lq*16;
    const uint32_t wa = (uint32_t)__cvta_generic_to_shared(ws2) + lr*130*8;

    float* hb0 = g_h[LAYER][cell][0];
    float* hb1 = g_h[LAYER][cell][1];
    int* flags = &g_flag[LAYER][cell][0];
    int* myf   = &g_flag[LAYER][cell][p];
    const float* zbase = g_zq + ((size_t)cell*512 + p*4 + u)*64 + b;

    float c = 0.f;
    __syncthreads();

    for (int t = 0; t < SEQ; t++) {
        const float* zp = zbase + (size_t)t*65536;      // t*1024*64
        float z0 = __ldcs(zp);
        float z1 = __ldcs(zp + 8192);                   // gate stride 128*64
        float z2 = __ldcs(zp + 16384);
        float z3 = __ldcs(zp + 24576);

        const float4* hsrc = (const float4*)((t & 1) ? hb1 : hb0);
#pragma unroll
        for (int i = 0; i < 8; i++) {
            int q = tid + i*256;
            float4 v = __ldcg(hsrc + q);
            *(float4*)(hs + q*4) = v;
        }
        __syncthreads();

        u64 a0 = 0ull, a1 = 0ull;
#pragma unroll
        for (int k = 0; k < 128; k += 2) {
            u64 h0p0,h0p1,h1p0,h1p1,w0,w1;
            lds2(h0p0,h0p1, ha + k*256);
            lds2(h1p0,h1p1, ha + k*256 + 256);
            lds2(w0,w1, wa + k*8);
            ffma2(a0,h0p0,w0); ffma2(a1,h0p1,w0);
            ffma2(a0,h1p0,w1); ffma2(a1,h1p1,w1);
        }
        {
            float x0,x1,x2,x3;
            unpk(x0,x1,a0); unpk(x2,x3,a1);
            *(float2*)&zsm[lr*66 + lq*4]     = make_float2(x0,x1);
            *(float2*)&zsm[lr*66 + lq*4 + 2] = make_float2(x2,x3);
        }
        __syncthreads();

        float zi = z0 + zsm[(0*4+u)*66 + b];
        float zf = z1 + zsm[(1*4+u)*66 + b];
        float zg = z2 + zsm[(2*4+u)*66 + b];
        float zo = z3 + zsm[(3*4+u)*66 + b];
        float ig = sigm(zi), fg = sigm(zf), gg = tanh_s(zg), og = sigm(zo);
        c = fg*c + ig*gg;
        float h = og * tanh_s(c);

        float* hdst = (t & 1) ? hb0 : hb1;
        hdst[(p*4+u)*64 + b] = h;
        ys[((size_t)t*64 + b)*256 + cell*128 + p*4 + u] = h;

        __syncthreads();
        if (tid == 0) {
            __threadfence();
            asm volatile("st.release.gpu.global.s32 [%0], %1;" :: "l"(myf), "r"(t+1) : "memory");
        }
        if (tid < 32) {
            const int* fp = flags + tid;
            while (ldacq(fp) <= t) { }
        }
        __syncthreads();
    }
}

// ---------------- final FC + sigmoid ----------------------------------------
__global__ void __launch_bounds__(256) fc_kernel(
    const float* __restrict__ fcw, const float* __restrict__ fcb,
    float* __restrict__ out)
{
    int gtid = blockIdx.x*blockDim.x + threadIdx.x;
    int row = gtid >> 5, lane = gtid & 31;
    if (row >= NROWS) return;
    const float* y = g_ys1 + (size_t)row*256;
    float s = 0.f;
#pragma unroll
    for (int i = 0; i < 8; i++) s += y[lane + i*32] * __ldg(fcw + lane + i*32);
#pragma unroll
    for (int o = 16; o; o >>= 1) s += __shfl_xor_sync(0xffffffffu, s, o);
    if (lane == 0) out[row] = 1.f / (1.f + __expf(-(s + fcb[0])));
}

// ---------------- launch -----------------------------------------------------
extern "C" void kernel_launch(void* const* d_in, const int* in_sizes, int n_in,
                              void* d_out, int out_size)
{
    const float* x     = (const float*)d_in[0];
    const float* wih0f = (const float*)d_in[1];
    const float* whh0f = (const float*)d_in[2];
    const float* b0f   = (const float*)d_in[3];
    const float* wih0b = (const float*)d_in[4];
    const float* whh0b = (const float*)d_in[5];
    const float* b0b   = (const float*)d_in[6];
    const float* wih1f = (const float*)d_in[7];
    const float* whh1f = (const float*)d_in[8];
    const float* b1f   = (const float*)d_in[9];
    const float* wih1b = (const float*)d_in[10];
    const float* whh1b = (const float*)d_in[11];
    const float* b1b   = (const float*)d_in[12];
    const float* fcw   = (const float*)d_in[13];
    const float* fcb   = (const float*)d_in[14];
    float* out = (float*)d_out;

    cudaFuncSetAttribute(recur_kernel<0>, cudaFuncAttributeMaxDynamicSharedMemorySize, REC_SMEM);
    cudaFuncSetAttribute(recur_kernel<1>, cudaFuncAttributeMaxDynamicSharedMemorySize, REC_SMEM);

    init_kernel<<<64, 256>>>();

    dim3 ggrid(8, SEQ/2);
    gemm_kernel<DIM, 0><<<ggrid, 256>>>(x, wih0f, wih0b, b0f, b0b);
    recur_kernel<0><<<64, 256, REC_SMEM>>>(whh0f, whh0b);

    gemm_kernel<256, 1><<<ggrid, 256>>>(nullptr, wih1f, wih1b, b1f, b1b);
    recur_kernel<1><<<64, 256, REC_SMEM>>>(whh1f, whh1b);

    fc_kernel<<<(NROWS*32)/256, 256>>>(fcw, fcb, out);
}

// round 4
// speedup vs baseline: 4.5670x; 4.5670x over previous
#include <cuda_runtime.h>
#include <cstdint>

#define SEQ   4096
#define BATCH 64
#define DIM   96
#define HID   128
#define NROWS (SEQ*BATCH)

using u64 = unsigned long long;

// ---------------- scratch (static device globals) ---------------------------
// z layout: [row = t*64+b][n = cell*512 + gate*128 + unit]  (+1 step overrun pad)
__device__ float g_zx0[(size_t)NROWS*1024 + 65536];
__device__ float g_zx1[(size_t)NROWS*1024 + 65536];
__device__ float g_ys0[(size_t)NROWS*256];    // [t][b][2H]
__device__ float g_ys1[(size_t)NROWS*256];

// ---------------- helpers ----------------------------------------------------
__device__ __forceinline__ float sigm(float x)   { return 1.f/(1.f+__expf(-x)); }
__device__ __forceinline__ float tanh_s(float x) { float e=__expf(2.f*x); return 1.f-2.f/(e+1.f); }
__device__ __forceinline__ void ffma2(u64 &d, u64 a, u64 b) {
    asm volatile("fma.rn.f32x2 %0, %1, %2, %0;" : "+l"(d) : "l"(a), "l"(b));
}
__device__ __forceinline__ void lds2(u64 &a, u64 &b, uint32_t addr) {
    asm volatile("ld.shared.v2.u64 {%0,%1}, [%2];" : "=l"(a), "=l"(b) : "r"(addr));
}
__device__ __forceinline__ u64 lds1(uint32_t addr) {
    u64 a; asm volatile("ld.shared.u64 %0, [%1];" : "=l"(a) : "r"(addr)); return a;
}
__device__ __forceinline__ void unpk(float &lo, float &hi, u64 v) {
    asm volatile("mov.b64 {%0,%1}, %2;" : "=f"(lo), "=f"(hi) : "l"(v));
}

// ---------------- input-projection GEMM (round-1 proven version) ------------
// Z[row][n] = bias[n] + sum_k A[row][k]*W[n][k].  128(M)x64(N) tile, 256 thr.
template<int K, int LAYER>
__global__ void __launch_bounds__(256) gemm_kernel(
    const float* __restrict__ Aext,
    const float* __restrict__ Wf, const float* __restrict__ Wb,
    const float* __restrict__ bf, const float* __restrict__ bb)
{
    __shared__ float As[16][132];
    __shared__ float Bs[16][68];

    const float* A = (LAYER == 0) ? Aext : (const float*)g_ys0;
    float*       Z = (LAYER == 0) ? g_zx0 : g_zx1;

    int tid = threadIdx.x;
    int m0 = blockIdx.y * 128;
    int n0 = blockIdx.x * 64;

    const float* W    = (n0 < 512) ? (Wf + (size_t)n0*K) : (Wb + (size_t)(n0-512)*K);
    const float* bias = (n0 < 512) ? (bf + n0) : (bb + (n0-512));

    int ty = tid >> 4;
    int tx = tid & 15;

    float acc[8][4];
#pragma unroll
    for (int i = 0; i < 8; i++)
#pragma unroll
        for (int j = 0; j < 4; j++) acc[i][j] = 0.f;

    for (int k0 = 0; k0 < K; k0 += 16) {
#pragma unroll
        for (int i = 0; i < 2; i++) {
            int q = tid + i*256, r = q >> 2, kq = q & 3;
            float4 a = *(const float4*)(A + (size_t)(m0+r)*K + k0 + kq*4);
            As[kq*4+0][r]=a.x; As[kq*4+1][r]=a.y; As[kq*4+2][r]=a.z; As[kq*4+3][r]=a.w;
        }
        {
            int n = tid >> 2, kq = tid & 3;
            float4 w = *(const float4*)(W + (size_t)n*K + k0 + kq*4);
            Bs[kq*4+0][n]=w.x; Bs[kq*4+1][n]=w.y; Bs[kq*4+2][n]=w.z; Bs[kq*4+3][n]=w.w;
        }
        __syncthreads();
#pragma unroll
        for (int kk = 0; kk < 16; kk++) {
            float a0[8], b0[4];
            *(float4*)&a0[0] = *(const float4*)&As[kk][ty*8];
            *(float4*)&a0[4] = *(const float4*)&As[kk][ty*8+4];
            *(float4*)&b0[0] = *(const float4*)&Bs[kk][tx*4];
#pragma unroll
            for (int i = 0; i < 8; i++)
#pragma unroll
                for (int j = 0; j < 4; j++) acc[i][j] += a0[i]*b0[j];
        }
        __syncthreads();
    }

    float4 bv = *(const float4*)(bias + tx*4);
#pragma unroll
    for (int i = 0; i < 8; i++) {
        float4 o;
        o.x = acc[i][0]+bv.x; o.y = acc[i][1]+bv.y;
        o.z = acc[i][2]+bv.z; o.w = acc[i][3]+bv.w;
        *(float4*)(Z + (size_t)(m0+ty*8+i)*1024 + n0 + tx*4) = o;
    }
}

// ---------------- recurrence: one CTA per (cell, batch) ----------------------
// 128 CTAs x 512 threads. Thread j owns Whh row j (gate=j>>7, unit=j&127):
// 96 weights in regs (48 f32x2 k-pairs), 32 in smem. h[128] in smem (broadcast
// reads). No inter-CTA communication at all; 2 __syncthreads per step.
#define RSMEM (65536 + 512 + 2048)

template<int LAYER>
__global__ void __launch_bounds__(512, 1) recur_kernel(
    const float* __restrict__ whhf, const float* __restrict__ whhb)
{
    extern __shared__ char smraw[];
    u64*   wsm = (u64*)smraw;                       // [16 kp][512 j]
    float* hs  = (float*)(smraw + 65536);           // [128]
    float* zs  = (float*)(smraw + 65536 + 512);     // [512]

    const int tid  = threadIdx.x;                   // = j
    const int cell = blockIdx.x >> 6;
    const int b    = blockIdx.x & 63;
    const float* whh = cell ? whhb : whhf;
    const float* zx  = LAYER ? g_zx1 : g_zx0;
    float*       ys  = LAYER ? g_ys1 : g_ys0;

    // one-time: load row j weights -> 48 reg pairs + 16 smem pairs
    const u64* wrow = (const u64*)whh + (size_t)tid*64;
    u64 wreg[48];
#pragma unroll
    for (int q = 0; q < 48; q++) wreg[q] = __ldg(wrow + q);
#pragma unroll
    for (int q = 0; q < 16; q++) wsm[q*512 + tid] = __ldg(wrow + 48 + q);

    if (tid < 128) hs[tid] = 0.f;

    uint32_t hs_s  = (uint32_t)__cvta_generic_to_shared(hs);
    uint32_t wsm_s = (uint32_t)__cvta_generic_to_shared(wsm);

    const float* zptr = zx + (size_t)b*1024 + cell*512 + tid;   // stride 65536/t
    float* ysp = ys + (size_t)b*256 + cell*128 + tid;           // stride 16384/t
    float zcur = __ldcs(zptr);
    float c = 0.f;

    __syncthreads();

    for (int t = 0; t < SEQ; t++) {
        float znext = __ldcs(zptr + (size_t)(t+1)*65536);       // pad covers t=SEQ-1

        u64 acc0 = 0ull, acc1 = 0ull;
#pragma unroll
        for (int q = 0; q < 48; q += 2) {                       // k in [0,96)
            u64 ha, hb;
            lds2(ha, hb, hs_s + q*8);
            ffma2(acc0, wreg[q],   ha);
            ffma2(acc1, wreg[q+1], hb);
        }
#pragma unroll
        for (int kp = 0; kp < 16; kp += 2) {                    // k in [96,128)
            u64 ha, hb;
            lds2(ha, hb, hs_s + 384 + kp*8);
            u64 wa = lds1(wsm_s + (kp*512     + tid)*8);
            u64 wb = lds1(wsm_s + ((kp+1)*512 + tid)*8);
            ffma2(acc0, wa, ha);
            ffma2(acc1, wb, hb);
        }
        float x0,x1,x2,x3;
        unpk(x0,x1,acc0); unpk(x2,x3,acc1);
        zs[tid] = ((x0+x1)+(x2+x3)) + zcur;
        zcur = znext;
        __syncthreads();

        if (tid < 128) {
            float zi = zs[tid], zf = zs[128+tid], zg = zs[256+tid], zo = zs[384+tid];
            float ig = sigm(zi), fg = sigm(zf), gg = tanh_s(zg), og = sigm(zo);
            c = fg*c + ig*gg;
            float h = og * tanh_s(c);
            hs[tid] = h;
            ysp[(size_t)t*16384] = h;
        }
        __syncthreads();
    }
}

// ---------------- final FC + sigmoid ----------------------------------------
__global__ void __launch_bounds__(256) fc_kernel(
    const float* __restrict__ fcw, const float* __restrict__ fcb,
    float* __restrict__ out)
{
    int gtid = blockIdx.x*blockDim.x + threadIdx.x;
    int row = gtid >> 5, lane = gtid & 31;
    if (row >= NROWS) return;
    const float* y = g_ys1 + (size_t)row*256;
    float s = 0.f;
#pragma unroll
    for (int i = 0; i < 8; i++) s += y[lane + i*32] * __ldg(fcw + lane + i*32);
#pragma unroll
    for (int o = 16; o; o >>= 1) s += __shfl_xor_sync(0xffffffffu, s, o);
    if (lane == 0) out[row] = 1.f/(1.f + __expf(-(s + fcb[0])));
}

// ---------------- launch -----------------------------------------------------
extern "C" void kernel_launch(void* const* d_in, const int* in_sizes, int n_in,
                              void* d_out, int out_size)
{
    const float* x     = (const float*)d_in[0];
    const float* wih0f = (const float*)d_in[1];
    const float* whh0f = (const float*)d_in[2];
    const float* b0f   = (const float*)d_in[3];
    const float* wih0b = (const float*)d_in[4];
    const float* whh0b = (const float*)d_in[5];
    const float* b0b   = (const float*)d_in[6];
    const float* wih1f = (const float*)d_in[7];
    const float* whh1f = (const float*)d_in[8];
    const float* b1f   = (const float*)d_in[9];
    const float* wih1b = (const float*)d_in[10];
    const float* whh1b = (const float*)d_in[11];
    const float* b1b   = (const float*)d_in[12];
    const float* fcw   = (const float*)d_in[13];
    const float* fcb   = (const float*)d_in[14];
    float* out = (float*)d_out;

    cudaFuncSetAttribute(recur_kernel<0>, cudaFuncAttributeMaxDynamicSharedMemorySize, RSMEM);
    cudaFuncSetAttribute(recur_kernel<1>, cudaFuncAttributeMaxDynamicSharedMemorySize, RSMEM);

    dim3 ggrid(16, NROWS/128);
    gemm_kernel<DIM, 0><<<ggrid, 256>>>(x, wih0f, wih0b, b0f, b0b);
    recur_kernel<0><<<128, 512, RSMEM>>>(whh0f, whh0b);

    gemm_kernel<256, 1><<<ggrid, 256>>>(nullptr, wih1f, wih1b, b1f, b1b);
    recur_kernel<1><<<128, 512, RSMEM>>>(whh1f, whh1b);

    fc_kernel<<<(NROWS*32)/256, 256>>>(fcw, fcb, out);
}

// round 5
// speedup vs baseline: 5.6031x; 1.2269x over previous
#include <cuda_runtime.h>
#include <cstdint>

#define SEQ   4096
#define BATCH 64
#define DIM   96
#define HID   128
#define NROWS (SEQ*BATCH)

using u64 = unsigned long long;

// ---------------- scratch (static device globals) ---------------------------
__device__ float g_zx0[(size_t)NROWS*1024 + 65536];  // [row=t*64+b][n], +1 step pad
__device__ float g_zx1[(size_t)NROWS*1024 + 65536];
__device__ float g_ys0[(size_t)NROWS*256];           // [t][b][2H]
__device__ float g_ys1[(size_t)NROWS*256];

// ---------------- helpers ----------------------------------------------------
__device__ __forceinline__ float sigm(float x)   { return 1.f/(1.f+__expf(-x)); }
__device__ __forceinline__ float tanh_s(float x) { float e=__expf(2.f*x); return 1.f-2.f/(e+1.f); }
__device__ __forceinline__ void ffma2(u64 &d, u64 a, u64 b) {
    asm volatile("fma.rn.f32x2 %0, %1, %2, %0;" : "+l"(d) : "l"(a), "l"(b));
}
__device__ __forceinline__ void lds2(u64 &a, u64 &b, uint32_t addr) {
    asm volatile("ld.shared.v2.u64 {%0,%1}, [%2];" : "=l"(a), "=l"(b) : "r"(addr));
}
__device__ __forceinline__ u64 lds1(uint32_t addr) {
    u64 a; asm volatile("ld.shared.u64 %0, [%1];" : "=l"(a) : "r"(addr)); return a;
}
__device__ __forceinline__ void unpk(float &lo, float &hi, u64 v) {
    asm volatile("mov.b64 {%0,%1}, %2;" : "=f"(lo), "=f"(hi) : "l"(v));
}
__device__ __forceinline__ uint32_t f2tf32(float x) {
    uint32_t r; asm("cvt.rna.tf32.f32 %0, %1;" : "=r"(r) : "f"(x)); return r;
}
__device__ __forceinline__ void mma_tf32(float4 &c,
    uint32_t a0, uint32_t a1, uint32_t a2, uint32_t a3,
    uint32_t b0, uint32_t b1)
{
    asm volatile("mma.sync.aligned.m16n8k8.row.col.f32.tf32.tf32.f32 "
        "{%0,%1,%2,%3}, {%4,%5,%6,%7}, {%8,%9}, {%0,%1,%2,%3};"
        : "+f"(c.x), "+f"(c.y), "+f"(c.z), "+f"(c.w)
        : "r"(a0), "r"(a1), "r"(a2), "r"(a3), "r"(b0), "r"(b1));
}

// ---------------- input-projection GEMM: tf32 tensor cores -------------------
// Z[row][n] = bias[n] + sum_k A[row][k]*W[n][k]
// CTA tile 128(M) x 128(N), K-tile 32. 8 warps = 4(M) x 2(N); warp = 32x64.
// smem pad-36 layouts are conflict-free for the m16n8k8 fragment pattern.
template<int K, int LAYER>
__global__ void __launch_bounds__(256) mma_gemm(
    const float* __restrict__ Aext,
    const float* __restrict__ Wf, const float* __restrict__ Wb,
    const float* __restrict__ bf, const float* __restrict__ bb)
{
    __shared__ uint32_t As[128][36];
    __shared__ uint32_t Ws[128][36];

    const float* A = (LAYER == 0) ? Aext : (const float*)g_ys0;
    float*       Z = LAYER ? g_zx1 : g_zx0;

    const int n0 = blockIdx.x * 128;
    const int m0 = blockIdx.y * 128;
    const float* W    = (n0 < 512) ? (Wf + (size_t)n0*K) : (Wb + (size_t)(n0-512)*K);
    const float* bias = (n0 < 512) ? (bf + n0) : (bb + (n0-512));

    const int tid  = threadIdx.x;
    const int wid  = tid >> 5, lane = tid & 31;
    const int wm   = wid & 3,  wn   = wid >> 2;
    const int g    = lane >> 2, t   = lane & 3;

    float4 acc[2][8];
#pragma unroll
    for (int mi = 0; mi < 2; mi++)
#pragma unroll
        for (int ni = 0; ni < 8; ni++) acc[mi][ni] = make_float4(0.f,0.f,0.f,0.f);

    for (int k0 = 0; k0 < K; k0 += 32) {
#pragma unroll
        for (int i = 0; i < 4; i++) {
            int q = tid + i*256;
            int r = q >> 3, kq = q & 7;
            float4 av = *(const float4*)(A + (size_t)(m0+r)*K + k0 + kq*4);
            uint4 ua = { f2tf32(av.x), f2tf32(av.y), f2tf32(av.z), f2tf32(av.w) };
            *(uint4*)&As[r][kq*4] = ua;
            float4 wv = *(const float4*)(W + (size_t)r*K + k0 + kq*4);
            uint4 uw = { f2tf32(wv.x), f2tf32(wv.y), f2tf32(wv.z), f2tf32(wv.w) };
            *(uint4*)&Ws[r][kq*4] = uw;
        }
        __syncthreads();
#pragma unroll
        for (int kb = 0; kb < 32; kb += 8) {
            uint32_t a[2][4];
#pragma unroll
            for (int mi = 0; mi < 2; mi++) {
                int R = wm*32 + mi*16;
                a[mi][0] = As[R + g    ][kb + t    ];
                a[mi][1] = As[R + g + 8][kb + t    ];
                a[mi][2] = As[R + g    ][kb + t + 4];
                a[mi][3] = As[R + g + 8][kb + t + 4];
            }
#pragma unroll
            for (int ni = 0; ni < 8; ni++) {
                int N8 = wn*64 + ni*8;
                uint32_t b0 = Ws[N8 + g][kb + t    ];
                uint32_t b1 = Ws[N8 + g][kb + t + 4];
                mma_tf32(acc[0][ni], a[0][0], a[0][1], a[0][2], a[0][3], b0, b1);
                mma_tf32(acc[1][ni], a[1][0], a[1][1], a[1][2], a[1][3], b0, b1);
            }
        }
        __syncthreads();
    }

#pragma unroll
    for (int ni = 0; ni < 8; ni++) {
        int ncl = wn*64 + ni*8 + 2*t;                 // local col within 128-block
        float2 bv = *(const float2*)(bias + ncl);
#pragma unroll
        for (int mi = 0; mi < 2; mi++) {
            float4 cf = acc[mi][ni];
            int r0 = m0 + wm*32 + mi*16 + g;
            float2 o0 = { cf.x + bv.x, cf.y + bv.y };
            float2 o1 = { cf.z + bv.x, cf.w + bv.y };
            *(float2*)(Z + (size_t)r0*1024 + n0 + ncl)     = o0;
            *(float2*)(Z + (size_t)(r0+8)*1024 + n0 + ncl) = o1;
        }
    }
}

// ---------------- recurrence: one CTA per (cell, batch) — round-4 proven -----
#define RSMEM (65536 + 512 + 2048)

template<int LAYER>
__global__ void __launch_bounds__(512, 1) recur_kernel(
    const float* __restrict__ whhf, const float* __restrict__ whhb)
{
    extern __shared__ char smraw[];
    u64*   wsm = (u64*)smraw;                       // [16 kp][512 j]
    float* hs  = (float*)(smraw + 65536);           // [128]
    float* zs  = (float*)(smraw + 65536 + 512);     // [512]

    const int tid  = threadIdx.x;                   // = j (Whh row)
    const int cell = blockIdx.x >> 6;
    const int b    = blockIdx.x & 63;
    const float* whh = cell ? whhb : whhf;
    const float* zx  = LAYER ? g_zx1 : g_zx0;
    float*       ys  = LAYER ? g_ys1 : g_ys0;

    const u64* wrow = (const u64*)whh + (size_t)tid*64;
    u64 wreg[48];
#pragma unroll
    for (int q = 0; q < 48; q++) wreg[q] = __ldg(wrow + q);
#pragma unroll
    for (int q = 0; q < 16; q++) wsm[q*512 + tid] = __ldg(wrow + 48 + q);

    if (tid < 128) hs[tid] = 0.f;

    uint32_t hs_s  = (uint32_t)__cvta_generic_to_shared(hs);
    uint32_t wsm_s = (uint32_t)__cvta_generic_to_shared(wsm);

    const float* zptr = zx + (size_t)b*1024 + cell*512 + tid;
    float* ysp = ys + (size_t)b*256 + cell*128 + tid;
    float zcur = __ldcs(zptr);
    float c = 0.f;

    __syncthreads();

    for (int t = 0; t < SEQ; t++) {
        float znext = __ldcs(zptr + (size_t)(t+1)*65536);

        u64 acc0 = 0ull, acc1 = 0ull;
#pragma unroll
        for (int q = 0; q < 48; q += 2) {
            u64 ha, hb;
            lds2(ha, hb, hs_s + q*8);
            ffma2(acc0, wreg[q],   ha);
            ffma2(acc1, wreg[q+1], hb);
        }
#pragma unroll
        for (int kp = 0; kp < 16; kp += 2) {
            u64 ha, hb;
            lds2(ha, hb, hs_s + 384 + kp*8);
            u64 wa = lds1(wsm_s + (kp*512     + tid)*8);
            u64 wb = lds1(wsm_s + ((kp+1)*512 + tid)*8);
            ffma2(acc0, wa, ha);
            ffma2(acc1, wb, hb);
        }
        float x0,x1,x2,x3;
        unpk(x0,x1,acc0); unpk(x2,x3,acc1);
        zs[tid] = ((x0+x1)+(x2+x3)) + zcur;
        zcur = znext;
        __syncthreads();

        if (tid < 128) {
            float zi = zs[tid], zf = zs[128+tid], zg = zs[256+tid], zo = zs[384+tid];
            float ig = sigm(zi), fg = sigm(zf), gg = tanh_s(zg), og = sigm(zo);
            c = fg*c + ig*gg;
            float h = og * tanh_s(c);
            hs[tid] = h;
            ysp[(size_t)t*16384] = h;
        }
        __syncthreads();
    }
}

// ---------------- final FC + sigmoid ----------------------------------------
__global__ void __launch_bounds__(256) fc_kernel(
    const float* __restrict__ fcw, const float* __restrict__ fcb,
    float* __restrict__ out)
{
    int gtid = blockIdx.x*blockDim.x + threadIdx.x;
    int row = gtid >> 5, lane = gtid & 31;
    if (row >= NROWS) return;
    const float* y = g_ys1 + (size_t)row*256;
    float s = 0.f;
#pragma unroll
    for (int i = 0; i < 8; i++) s += y[lane + i*32] * __ldg(fcw + lane + i*32);
#pragma unroll
    for (int o = 16; o; o >>= 1) s += __shfl_xor_sync(0xffffffffu, s, o);
    if (lane == 0) out[row] = 1.f/(1.f + __expf(-(s + fcb[0])));
}

// ---------------- launch -----------------------------------------------------
extern "C" void kernel_launch(void* const* d_in, const int* in_sizes, int n_in,
                              void* d_out, int out_size)
{
    const float* x     = (const float*)d_in[0];
    const float* wih0f = (const float*)d_in[1];
    const float* whh0f = (const float*)d_in[2];
    const float* b0f   = (const float*)d_in[3];
    const float* wih0b = (const float*)d_in[4];
    const float* whh0b = (const float*)d_in[5];
    const float* b0b   = (const float*)d_in[6];
    const float* wih1f = (const float*)d_in[7];
    const float* whh1f = (const float*)d_in[8];
    const float* b1f   = (const float*)d_in[9];
    const float* wih1b = (const float*)d_in[10];
    const float* whh1b = (const float*)d_in[11];
    const float* b1b   = (const float*)d_in[12];
    const float* fcw   = (const float*)d_in[13];
    const float* fcb   = (const float*)d_in[14];
    float* out = (float*)d_out;

    cudaFuncSetAttribute(recur_kernel<0>, cudaFuncAttributeMaxDynamicSharedMemorySize, RSMEM);
    cudaFuncSetAttribute(recur_kernel<1>, cudaFuncAttributeMaxDynamicSharedMemorySize, RSMEM);

    dim3 ggrid(8, NROWS/128);
    mma_gemm<DIM, 0><<<ggrid, 256>>>(x, wih0f, wih0b, b0f, b0b);
    recur_kernel<0><<<128, 512, RSMEM>>>(whh0f, whh0b);

    mma_gemm<256, 1><<<ggrid, 256>>>(nullptr, wih1f, wih1b, b1f, b1b);
    recur_kernel<1><<<128, 512, RSMEM>>>(whh1f, whh1b);

    fc_kernel<<<(NROWS*32)/256, 256>>>(fcw, fcb, out);
}